// round 12
// baseline (speedup 1.0000x reference)
#include <cuda_runtime.h>
#include <cuda_fp16.h>
#include <cstdint>

// Zonotope propagation: D=1024 -> H=4096 -> H=4096 -> O=10
// E2 = W2 @ Baug via single-pass fp16 mma.sync (fp32 acc), rel_err ~6e-6.
// R11: single-barrier write-ahead pipeline in k3 (STS/cpB into stage kg+2
//      while MMA runs on stage kg) -> 128 barriers instead of 256, full
//      overlap of A-convert with tensor work.

#define DD 1024
#define HH 4096
#define OO 10
#define NE 1024
#define NC3 1027
#define SE3 1056
#define KS3 32
#define NJT 8

#define C_EPS   0.01f
#define C_MEAN  0.1307f
#define C_SIGMA 0.3081f

// ---- device scratch ----
__device__ float g_s1[HH];
__device__ float g_t1[HH];
__device__ float g_v1p[HH];
__device__ float g_d[DD];
__device__ __half g_BTh[(size_t)NE * HH];      // 8.4 MB (BaugT fp16, K-major)
__device__ float g_E2s[(size_t)HH * NE];       // 16.8 MB
__device__ float g_rpart[NJT][HH];
__device__ float g_tcol[HH];
__device__ float g_vcol[HH];
__device__ float g_s2[HH];
__device__ float g_t2[HH];
__device__ float g_v2p[HH];
__device__ float g_E3p[KS3 * OO * SE3];

// ================= PTX helpers =================
static __device__ __forceinline__ uint32_t smem_u32(const void* p) {
    uint32_t a;
    asm("{ .reg .u64 t; cvta.to.shared.u64 t, %1; cvt.u32.u64 %0, t; }" : "=r"(a) : "l"(p));
    return a;
}
static __device__ __forceinline__ void cp16(uint32_t dst, const void* src) {
    asm volatile("cp.async.cg.shared.global [%0], [%1], 16;" :: "r"(dst), "l"(src));
}
static __device__ __forceinline__ void cp_commit() {
    asm volatile("cp.async.commit_group;" ::: "memory");
}
template <int N> static __device__ __forceinline__ void cp_wait() {
    asm volatile("cp.async.wait_group %0;" :: "n"(N) : "memory");
}
#define LDSM4(r0, r1, r2, r3, addr) \
    asm volatile("ldmatrix.sync.aligned.m8n8.x4.shared.b16 {%0,%1,%2,%3}, [%4];" \
                 : "=r"(r0), "=r"(r1), "=r"(r2), "=r"(r3) : "r"(addr))
#define MMA16816F(c, a, b) \
    asm volatile("mma.sync.aligned.m16n8k16.row.col.f32.f16.f16.f32 " \
                 "{%0,%1,%2,%3}, {%4,%5,%6,%7}, {%8,%9}, {%0,%1,%2,%3};" \
                 : "+f"((c)[0]), "+f"((c)[1]), "+f"((c)[2]), "+f"((c)[3]) \
                 : "r"((a)[0]), "r"((a)[1]), "r"((a)[2]), "r"((a)[3]), \
                   "r"((b)[0]), "r"((b)[1]))
#define STS128(addr, u0, u1, u2, u3) \
    asm volatile("st.shared.v4.b32 [%0], {%1,%2,%3,%4};" \
                 :: "r"(addr), "r"(u0), "r"(u1), "r"(u2), "r"(u3) : "memory")

static __device__ __forceinline__ void relu_params(float v, float r,
                                                   float& s, float& t, float& vn) {
    float u = v + r;
    float l = v - r;
    if (u <= 0.f)       { s = 0.f; t = 0.f; vn = 0.f; }
    else if (l < 0.f)   { float slope = u / (u - l); float term = (1.f - slope) * u * 0.5f;
                          s = slope; t = term; vn = slope * v + term; }
    else                { s = 1.f; t = 0.f; vn = v; }
}
static __device__ __forceinline__ uint32_t h2u(__half2 h) {
    return *reinterpret_cast<uint32_t*>(&h);
}

// ---- K01: fused init + layer-1 ----
__global__ void k01_layer1(const float* __restrict__ in,
                           const float* __restrict__ W1, const float* __restrict__ b1) {
    __shared__ __align__(16) float sv0[DD];
    __shared__ __align__(16) float sd[DD];
    const int tid = threadIdx.x;
    for (int j = tid; j < DD; j += 256) {
        float x  = in[j];
        float up = fminf(x + C_EPS, 1.f);
        float lo = fmaxf(x - C_EPS, 0.f);
        float val = up + lo;
        sv0[j] = (val - C_MEAN) / C_SIGMA;
        sd[j]  = up / C_SIGMA;
    }
    __syncthreads();
    if (blockIdx.x == 0) {
        for (int j = tid; j < DD; j += 256) g_d[j] = sd[j];
    }
    int row  = blockIdx.x * 8 + (tid >> 5);
    int lane = tid & 31;
    const float* w = W1 + (size_t)row * DD;
    float sv = 0.f, sr = 0.f;
    #pragma unroll
    for (int j = lane * 4; j < DD; j += 128) {
        float4 wv = *(const float4*)(w + j);
        float4 v  = *(const float4*)(sv0 + j);
        float4 dd = *(const float4*)(sd + j);
        sv += wv.x * v.x + wv.y * v.y + wv.z * v.z + wv.w * v.w;
        sr += fabsf(wv.x) * dd.x + fabsf(wv.y) * dd.y
            + fabsf(wv.z) * dd.z + fabsf(wv.w) * dd.w;
    }
    #pragma unroll
    for (int o = 16; o; o >>= 1) {
        sv += __shfl_xor_sync(0xffffffffu, sv, o);
        sr += __shfl_xor_sync(0xffffffffu, sr, o);
    }
    if (lane == 0) {
        float v = sv + b1[row];
        float s, t, vn;
        relu_params(v, sr, s, t, vn);
        g_s1[row] = s; g_t1[row] = t; g_v1p[row] = vn;
    }
}

// ---- K2b: BaugT rows 0..1023 in fp16 ----
__global__ void k2b_buildBT(const float* __restrict__ W1) {
    __shared__ float ts[32][33];
    int k0 = blockIdx.x * 32;
    int j0 = blockIdx.y * 32;
    int tx = threadIdx.x & 31, ty = threadIdx.x >> 5;
    #pragma unroll
    for (int r = 0; r < 4; r++) {
        int k = k0 + ty + r * 8;
        ts[ty + r * 8][tx] = W1[(size_t)k * DD + j0 + tx] * g_s1[k];
    }
    __syncthreads();
    #pragma unroll
    for (int r = 0; r < 4; r++) {
        int j = j0 + ty + r * 8;
        float x = ts[tx][ty + r * 8] * g_d[j];
        g_BTh[(size_t)j * HH + k0 + tx] = __float2half_rn(x);
    }
}

// ---- K3b: t/v columns (side stream) ----
__global__ void k3b_tv(const float* __restrict__ W2) {
    int row  = blockIdx.x * 8 + (threadIdx.x >> 5);
    int lane = threadIdx.x & 31;
    const float* w = W2 + (size_t)row * HH;
    float st = 0.f, sv = 0.f;
    for (int j = lane * 4; j < HH; j += 128) {
        float4 wv = *(const float4*)(w + j);
        float4 tt = *(const float4*)(g_t1 + j);
        float4 vv = *(const float4*)(g_v1p + j);
        st += wv.x * tt.x + wv.y * tt.y + wv.z * tt.z + wv.w * tt.w;
        sv += wv.x * vv.x + wv.y * vv.y + wv.z * vv.z + wv.w * vv.w;
    }
    #pragma unroll
    for (int o = 16; o; o >>= 1) {
        st += __shfl_xor_sync(0xffffffffu, st, o);
        sv += __shfl_xor_sync(0xffffffffu, sv, o);
    }
    if (lane == 0) { g_tcol[row] = st; g_vcol[row] = sv; }
}

// ================== K3: fp16 GEMM, single-barrier write-ahead pipeline =======
// Stage 16KB: A-fp16 @0 (STS-converted from fp32 W2), B-fp16 @8K (cp.async).
// 3-stage ring; in iter kg, prep stage (kg+2)%3 while MMA runs on kg%3.
#define K3_STG 16384
#define K3_SMEM (3 * K3_STG)
#define NKG3 128

__global__ __launch_bounds__(128, 2) void k3_mma(const float* __restrict__ W2) {
    extern __shared__ __align__(1024) unsigned char sm[];
    __shared__ float rs[2][128];
    const int tid  = threadIdx.x;
    const int lane = tid & 31;
    const int wid  = tid >> 5;
    const int warp_m = wid & 1;
    const int warp_n = wid >> 1;
    const int j0 = blockIdx.x * 128;
    const int i0 = blockIdx.y * 128;
    const uint32_t sbase = smem_u32(sm);

    const int ra = (lane & 7) + (((lane >> 3) & 1) << 3);
    const int ha = lane >> 4;
    const int rb = (lane & 7) + ((lane >> 4) << 3);
    const int hb = (lane >> 3) & 1;
    uint32_t offA[4][2], offB[4][2];
    #pragma unroll
    for (int mf = 0; mf < 4; mf++)
        #pragma unroll
        for (int kk = 0; kk < 2; kk++) {
            int row = warp_m * 64 + mf * 16 + ra;
            int c   = kk * 2 + ha;
            offA[mf][kk] = row * 64 + ((c ^ ((row >> 1) & 3)) << 4);
        }
    #pragma unroll
    for (int nf4 = 0; nf4 < 4; nf4++)
        #pragma unroll
        for (int kk = 0; kk < 2; kk++) {
            int row = warp_n * 64 + nf4 * 16 + rb;
            int c   = kk * 2 + hb;
            offB[nf4][kk] = 8192 + row * 64 + ((c ^ ((row >> 1) & 3)) << 4);
        }

    int crow[4], ccol[4];
    uint32_t csw[4];
    #pragma unroll
    for (int s = 0; s < 4; s++) {
        int q = s * 128 + tid;
        crow[s] = q >> 2; ccol[s] = q & 3;
        csw[s] = crow[s] * 64 + ((ccol[s] ^ ((crow[s] >> 1) & 3)) << 4);
    }

    float4 aA[4][2];
    auto ldgA = [&](int kg) {
        const int kgo = kg * 32;
        #pragma unroll
        for (int s = 0; s < 4; s++) {
            const float* gp = W2 + (size_t)(i0 + crow[s]) * HH + kgo + ccol[s] * 8;
            aA[s][0] = *(const float4*)gp;
            aA[s][1] = *(const float4*)(gp + 4);
        }
    };
    auto stsA = [&](int stage) {
        const uint32_t base = sbase + stage * K3_STG;
        #pragma unroll
        for (int s = 0; s < 4; s++) {
            __half2 h0 = __floats2half2_rn(aA[s][0].x, aA[s][0].y);
            __half2 h1 = __floats2half2_rn(aA[s][0].z, aA[s][0].w);
            __half2 h2 = __floats2half2_rn(aA[s][1].x, aA[s][1].y);
            __half2 h3 = __floats2half2_rn(aA[s][1].z, aA[s][1].w);
            STS128(base + csw[s], h2u(h0), h2u(h1), h2u(h2), h2u(h3));
        }
    };
    auto cpB = [&](int stage, int kg) {
        const uint32_t base = sbase + stage * K3_STG + 8192;
        const int kgo = kg * 32;
        #pragma unroll
        for (int s = 0; s < 4; s++)
            cp16(base + csw[s], g_BTh + (size_t)(j0 + crow[s]) * HH + kgo + ccol[s] * 8);
        cp_commit();
    };

    float acc[4][8][4];
    #pragma unroll
    for (int mf = 0; mf < 4; mf++)
        #pragma unroll
        for (int nf = 0; nf < 8; nf++)
            #pragma unroll
            for (int q = 0; q < 4; q++) acc[mf][nf][q] = 0.f;

    // prologue: stages 0,1 fully prepped; A(2) staged in regs
    ldgA(0); stsA(0); cpB(0, 0);
    ldgA(1); stsA(1); cpB(1, 1);
    ldgA(2);

    for (int kg = 0; kg < NKG3; ++kg) {
        if (kg + 1 == NKG3) cp_wait<0>();
        else                cp_wait<1>();
        __syncthreads();    // B(kg) joined; all warps done reading stage (kg-1)%3
        // prep stage (kg+2)%3 (== (kg-1)%3, now free) while MMA runs
        if (kg + 2 < NKG3) {
            const int ps = (kg + 2) % 3;
            stsA(ps);
            if (kg + 3 < NKG3) ldgA(kg + 3);
            cpB(ps, kg + 2);
        }
        const uint32_t base = sbase + (kg % 3) * K3_STG;
        #pragma unroll
        for (int kk = 0; kk < 2; kk++) {
            uint32_t a[4][4], bh[8][2];
            #pragma unroll
            for (int mf = 0; mf < 4; mf++)
                LDSM4(a[mf][0], a[mf][1], a[mf][2], a[mf][3], base + offA[mf][kk]);
            #pragma unroll
            for (int nf4 = 0; nf4 < 4; nf4++) {
                uint32_t r0, r1, r2, r3;
                LDSM4(r0, r1, r2, r3, base + offB[nf4][kk]);
                bh[nf4 * 2][0] = r0;     bh[nf4 * 2][1] = r1;
                bh[nf4 * 2 + 1][0] = r2; bh[nf4 * 2 + 1][1] = r3;
            }
            #pragma unroll
            for (int mf = 0; mf < 4; mf++)
                #pragma unroll
                for (int nf = 0; nf < 8; nf++)
                    MMA16816F(acc[mf][nf], a[mf], bh[nf]);
        }
    }

    // epilogue: store E2 tile + fused per-row |.| partial sums
    const int er = lane >> 2;
    const int ec = (lane & 3) * 2;
    #pragma unroll
    for (int mf = 0; mf < 4; mf++) {
        float sa = 0.f, sb = 0.f;
        #pragma unroll
        for (int nf = 0; nf < 8; nf++) {
            int row = i0 + warp_m * 64 + mf * 16 + er;
            int col = j0 + warp_n * 64 + nf * 8 + ec;
            *(float2*)(g_E2s + (size_t)row * NE + col)       = make_float2(acc[mf][nf][0], acc[mf][nf][1]);
            *(float2*)(g_E2s + (size_t)(row + 8) * NE + col) = make_float2(acc[mf][nf][2], acc[mf][nf][3]);
            sa += fabsf(acc[mf][nf][0]) + fabsf(acc[mf][nf][1]);
            sb += fabsf(acc[mf][nf][2]) + fabsf(acc[mf][nf][3]);
        }
        sa += __shfl_xor_sync(0xffffffffu, sa, 1);
        sa += __shfl_xor_sync(0xffffffffu, sa, 2);
        sb += __shfl_xor_sync(0xffffffffu, sb, 1);
        sb += __shfl_xor_sync(0xffffffffu, sb, 2);
        if ((lane & 3) == 0) {
            rs[warp_n][warp_m * 64 + mf * 16 + er]     = sa;
            rs[warp_n][warp_m * 64 + mf * 16 + 8 + er] = sb;
        }
    }
    __syncthreads();
    {
        int row = tid;
        float v = rs[0][row] + rs[1][row];
        g_rpart[blockIdx.x][i0 + row] = v;
    }
}

// ---- K4: combine jtile partials + ReLU params ----
__global__ void k4_relu2(const float* __restrict__ b2) {
    int row = blockIdx.x * 256 + threadIdx.x;
    float sr = 0.f;
    #pragma unroll
    for (int jt = 0; jt < NJT; jt++) sr += g_rpart[jt][row];
    sr += fabsf(g_tcol[row]);
    float v = g_vcol[row] + b2[row];
    float s, t, vn;
    relu_params(v, sr, s, t, vn);
    g_s2[row] = s; g_t2[row] = t; g_v2p[row] = vn;
}

// ---- K5: layer-3 partial GEMM (32-way deterministic k-split) ----
__global__ void k5_e3(const float* __restrict__ W3) {
    __shared__ float w3s[OO][128];
    __shared__ float s2s[128];
    const int jt = blockIdx.x, ks = blockIdx.y;
    const int k0 = ks * 128;
    const int tid = threadIdx.x;

    for (int idx = tid; idx < OO * 128; idx += 128) {
        int i = idx >> 7, kk = idx & 127;
        w3s[i][kk] = W3[(size_t)i * HH + k0 + kk];
    }
    s2s[tid] = g_s2[k0 + tid];
    __syncthreads();

    const int j = jt * 128 + tid;
    float acc[OO];
    #pragma unroll
    for (int i = 0; i < OO; i++) acc[i] = 0.f;

    if (j < 1024) {
        const float* e = g_E2s + (size_t)k0 * NE + j;
        for (int kk = 0; kk < 128; ++kk) {
            float bval = s2s[kk] * e[(size_t)kk * NE];
            #pragma unroll
            for (int i = 0; i < OO; i++) acc[i] += w3s[i][kk] * bval;
        }
    } else if (j == 1024) {
        for (int kk = 0; kk < 128; ++kk) {
            float bval = s2s[kk] * g_tcol[k0 + kk];
            #pragma unroll
            for (int i = 0; i < OO; i++) acc[i] += w3s[i][kk] * bval;
        }
    } else if (j == 1025) {
        for (int kk = 0; kk < 128; ++kk) {
            float bval = g_t2[k0 + kk];
            #pragma unroll
            for (int i = 0; i < OO; i++) acc[i] += w3s[i][kk] * bval;
        }
    } else if (j == 1026) {
        for (int kk = 0; kk < 128; ++kk) {
            float bval = g_v2p[k0 + kk];
            #pragma unroll
            for (int i = 0; i < OO; i++) acc[i] += w3s[i][kk] * bval;
        }
    }
    if (j < NC3) {
        #pragma unroll
        for (int i = 0; i < OO; i++)
            g_E3p[((size_t)ks * OO + i) * SE3 + j] = acc[i];
    }
}

// ---- K6 ----
__global__ void k6_final(const float* __restrict__ b3, float* __restrict__ out) {
    const int i = blockIdx.x;
    const int tid = threadIdx.x;
    __shared__ float red[256];
    __shared__ float vsh;
    float racc = 0.f;
    for (int j = tid; j < NC3; j += 256) {
        float s = 0.f;
        #pragma unroll
        for (int ks = 0; ks < KS3; ks++) s += g_E3p[((size_t)ks * OO + i) * SE3 + j];
        if (j < 1026) racc += fabsf(s);
        else          vsh = s + b3[i];
    }
    red[tid] = racc;
    __syncthreads();
    for (int o = 128; o; o >>= 1) {
        if (tid < o) red[tid] += red[tid + o];
        __syncthreads();
    }
    if (tid == 0) {
        float v = vsh, r = red[0];
        out[i]      = v + r;
        out[10 + i] = v - r;
    }
}

extern "C" void kernel_launch(void* const* d_in, const int* in_sizes, int n_in,
                              void* d_out, int out_size) {
    const float* inputs = (const float*)d_in[0];
    const float* W1     = (const float*)d_in[1];
    const float* b1     = (const float*)d_in[2];
    const float* W2     = (const float*)d_in[3];
    const float* b2     = (const float*)d_in[4];
    const float* W3     = (const float*)d_in[5];
    const float* b3     = (const float*)d_in[6];
    float* out = (float*)d_out;

    static cudaStream_t sB = nullptr;
    static cudaEvent_t evK = nullptr, evB = nullptr;
    if (!sB) {
        cudaStreamCreateWithFlags(&sB, cudaStreamNonBlocking);
        cudaEventCreateWithFlags(&evK, cudaEventDisableTiming);
        cudaEventCreateWithFlags(&evB, cudaEventDisableTiming);
        cudaFuncSetAttribute(k3_mma, cudaFuncAttributeMaxDynamicSharedMemorySize, K3_SMEM);
    }

    // main chain
    k01_layer1<<<HH / 8, 256>>>(inputs, W1, b1);

    // fork: t/v matvec on side stream (needs k01 only)
    cudaEventRecord(evK, 0);
    cudaStreamWaitEvent(sB, evK, 0);
    k3b_tv<<<HH / 8, 256, 0, sB>>>(W2);
    cudaEventRecord(evB, sB);

    dim3 g2b(HH / 32, DD / 32);
    k2b_buildBT<<<g2b, 256>>>(W1);

    dim3 g3(NE / 128, HH / 128);          // 256 CTAs, one wave @ occ 2
    k3_mma<<<g3, 128, K3_SMEM>>>(W2);

    cudaStreamWaitEvent(0, evB, 0);
    k4_relu2<<<HH / 256, 256>>>(b2);
    dim3 g5(9, KS3);
    k5_e3<<<g5, 128>>>(W3);
    k6_final<<<OO, 256>>>(b3, out);
}

// round 13
// speedup vs baseline: 1.0369x; 1.0369x over previous
#include <cuda_runtime.h>
#include <cuda_fp16.h>
#include <cstdint>

// Zonotope propagation: D=1024 -> H=4096 -> H=4096 -> O=10
// E2 = W2 @ Baug via single-pass fp16 mma.sync (fp32 acc), rel_err ~6e-6.
// R12: k4 fused into k5 (inline ReLU params per k-chunk); k2b rewritten at
//      64x64 tiles (4x fewer blocks, vectorized); k3 unchanged (at the
//      mma.sync per-SM ceiling on 128 active SMs).

#define DD 1024
#define HH 4096
#define OO 10
#define NE 1024
#define NC3 1027
#define SE3 1056
#define KS3 32
#define NJT 8

#define C_EPS   0.01f
#define C_MEAN  0.1307f
#define C_SIGMA 0.3081f

// ---- device scratch ----
__device__ float g_s1[HH];
__device__ float g_t1[HH];
__device__ float g_v1p[HH];
__device__ float g_d[DD];
__device__ __half g_BTh[(size_t)NE * HH];      // 8.4 MB (BaugT fp16, K-major)
__device__ float g_E2s[(size_t)HH * NE];       // 16.8 MB
__device__ float g_rpart[NJT][HH];
__device__ float g_tcol[HH];
__device__ float g_vcol[HH];
__device__ float g_E3p[KS3 * OO * SE3];

// ================= PTX helpers =================
static __device__ __forceinline__ uint32_t smem_u32(const void* p) {
    uint32_t a;
    asm("{ .reg .u64 t; cvta.to.shared.u64 t, %1; cvt.u32.u64 %0, t; }" : "=r"(a) : "l"(p));
    return a;
}
static __device__ __forceinline__ void cp16(uint32_t dst, const void* src) {
    asm volatile("cp.async.cg.shared.global [%0], [%1], 16;" :: "r"(dst), "l"(src));
}
static __device__ __forceinline__ void cp_commit() {
    asm volatile("cp.async.commit_group;" ::: "memory");
}
template <int N> static __device__ __forceinline__ void cp_wait() {
    asm volatile("cp.async.wait_group %0;" :: "n"(N) : "memory");
}
#define LDSM4(r0, r1, r2, r3, addr) \
    asm volatile("ldmatrix.sync.aligned.m8n8.x4.shared.b16 {%0,%1,%2,%3}, [%4];" \
                 : "=r"(r0), "=r"(r1), "=r"(r2), "=r"(r3) : "r"(addr))
#define MMA16816F(c, a, b) \
    asm volatile("mma.sync.aligned.m16n8k16.row.col.f32.f16.f16.f32 " \
                 "{%0,%1,%2,%3}, {%4,%5,%6,%7}, {%8,%9}, {%0,%1,%2,%3};" \
                 : "+f"((c)[0]), "+f"((c)[1]), "+f"((c)[2]), "+f"((c)[3]) \
                 : "r"((a)[0]), "r"((a)[1]), "r"((a)[2]), "r"((a)[3]), \
                   "r"((b)[0]), "r"((b)[1]))
#define STS128(addr, u0, u1, u2, u3) \
    asm volatile("st.shared.v4.b32 [%0], {%1,%2,%3,%4};" \
                 :: "r"(addr), "r"(u0), "r"(u1), "r"(u2), "r"(u3) : "memory")

static __device__ __forceinline__ void relu_params(float v, float r,
                                                   float& s, float& t, float& vn) {
    float u = v + r;
    float l = v - r;
    if (u <= 0.f)       { s = 0.f; t = 0.f; vn = 0.f; }
    else if (l < 0.f)   { float slope = u / (u - l); float term = (1.f - slope) * u * 0.5f;
                          s = slope; t = term; vn = slope * v + term; }
    else                { s = 1.f; t = 0.f; vn = v; }
}
static __device__ __forceinline__ uint32_t h2u(__half2 h) {
    return *reinterpret_cast<uint32_t*>(&h);
}

// ---- K01: fused init + layer-1 ----
__global__ void k01_layer1(const float* __restrict__ in,
                           const float* __restrict__ W1, const float* __restrict__ b1) {
    __shared__ __align__(16) float sv0[DD];
    __shared__ __align__(16) float sd[DD];
    const int tid = threadIdx.x;
    for (int j = tid; j < DD; j += 256) {
        float x  = in[j];
        float up = fminf(x + C_EPS, 1.f);
        float lo = fmaxf(x - C_EPS, 0.f);
        float val = up + lo;
        sv0[j] = (val - C_MEAN) / C_SIGMA;
        sd[j]  = up / C_SIGMA;
    }
    __syncthreads();
    if (blockIdx.x == 0) {
        for (int j = tid; j < DD; j += 256) g_d[j] = sd[j];
    }
    int row  = blockIdx.x * 8 + (tid >> 5);
    int lane = tid & 31;
    const float* w = W1 + (size_t)row * DD;
    float sv = 0.f, sr = 0.f;
    #pragma unroll
    for (int j = lane * 4; j < DD; j += 128) {
        float4 wv = *(const float4*)(w + j);
        float4 v  = *(const float4*)(sv0 + j);
        float4 dd = *(const float4*)(sd + j);
        sv += wv.x * v.x + wv.y * v.y + wv.z * v.z + wv.w * v.w;
        sr += fabsf(wv.x) * dd.x + fabsf(wv.y) * dd.y
            + fabsf(wv.z) * dd.z + fabsf(wv.w) * dd.w;
    }
    #pragma unroll
    for (int o = 16; o; o >>= 1) {
        sv += __shfl_xor_sync(0xffffffffu, sv, o);
        sr += __shfl_xor_sync(0xffffffffu, sr, o);
    }
    if (lane == 0) {
        float v = sv + b1[row];
        float s, t, vn;
        relu_params(v, sr, s, t, vn);
        g_s1[row] = s; g_t1[row] = t; g_v1p[row] = vn;
    }
}

// ---- K2b: BaugT in fp16, 64x64 tiles, 256 threads, vectorized ----
// BTh[j][k] = s1[k] * W1[k][j] * d[j]
__global__ void k2b_buildBT(const float* __restrict__ W1) {
    __shared__ float ts[64][65];
    const int k0 = blockIdx.x * 64;
    const int j0 = blockIdx.y * 64;
    const int tid = threadIdx.x;
    // load: 64 k-rows x 64 j-cols as float4 (4 per thread), scaled by s1[k]
    {
        const int kr = tid >> 4;          // 0..15
        const int c4 = (tid & 15) * 4;    // 0..60
        #pragma unroll
        for (int r = 0; r < 4; r++) {
            int krow = kr + r * 16;
            float s = g_s1[k0 + krow];
            float4 w = *(const float4*)(W1 + (size_t)(k0 + krow) * DD + j0 + c4);
            ts[krow][c4 + 0] = w.x * s;
            ts[krow][c4 + 1] = w.y * s;
            ts[krow][c4 + 2] = w.z * s;
            ts[krow][c4 + 3] = w.w * s;
        }
    }
    __syncthreads();
    // store: 64 j-rows x 64 k halves; 512 uint4 stores, 2 per thread
    #pragma unroll
    for (int w = 0; w < 2; w++) {
        int idx  = w * 256 + tid;
        int jrow = idx >> 3;              // 0..63
        int seg  = idx & 7;               // 8 halves per segment
        float dj = g_d[j0 + jrow];
        __half2 h[4];
        #pragma unroll
        for (int q = 0; q < 4; q++) {
            float a = ts[seg * 8 + q * 2][jrow] * dj;
            float b = ts[seg * 8 + q * 2 + 1][jrow] * dj;
            h[q] = __floats2half2_rn(a, b);
        }
        uint4 out = make_uint4(h2u(h[0]), h2u(h[1]), h2u(h[2]), h2u(h[3]));
        *(uint4*)(&g_BTh[(size_t)(j0 + jrow) * HH + k0 + seg * 8]) = out;
    }
}

// ---- K3b: t/v columns (side stream) ----
__global__ void k3b_tv(const float* __restrict__ W2) {
    int row  = blockIdx.x * 8 + (threadIdx.x >> 5);
    int lane = threadIdx.x & 31;
    const float* w = W2 + (size_t)row * HH;
    float st = 0.f, sv = 0.f;
    for (int j = lane * 4; j < HH; j += 128) {
        float4 wv = *(const float4*)(w + j);
        float4 tt = *(const float4*)(g_t1 + j);
        float4 vv = *(const float4*)(g_v1p + j);
        st += wv.x * tt.x + wv.y * tt.y + wv.z * tt.z + wv.w * tt.w;
        sv += wv.x * vv.x + wv.y * vv.y + wv.z * vv.z + wv.w * vv.w;
    }
    #pragma unroll
    for (int o = 16; o; o >>= 1) {
        st += __shfl_xor_sync(0xffffffffu, st, o);
        sv += __shfl_xor_sync(0xffffffffu, sv, o);
    }
    if (lane == 0) { g_tcol[row] = st; g_vcol[row] = sv; }
}

// ================== K3: fp16 GEMM, write-ahead pipeline (at HMMA ceiling) ====
#define K3_STG 16384
#define K3_SMEM (3 * K3_STG)
#define NKG3 128

__global__ __launch_bounds__(128, 2) void k3_mma(const float* __restrict__ W2) {
    extern __shared__ __align__(1024) unsigned char sm[];
    __shared__ float rs[2][128];
    const int tid  = threadIdx.x;
    const int lane = tid & 31;
    const int wid  = tid >> 5;
    const int warp_m = wid & 1;
    const int warp_n = wid >> 1;
    const int j0 = blockIdx.x * 128;
    const int i0 = blockIdx.y * 128;
    const uint32_t sbase = smem_u32(sm);

    const int ra = (lane & 7) + (((lane >> 3) & 1) << 3);
    const int ha = lane >> 4;
    const int rb = (lane & 7) + ((lane >> 4) << 3);
    const int hb = (lane >> 3) & 1;
    uint32_t offA[4][2], offB[4][2];
    #pragma unroll
    for (int mf = 0; mf < 4; mf++)
        #pragma unroll
        for (int kk = 0; kk < 2; kk++) {
            int row = warp_m * 64 + mf * 16 + ra;
            int c   = kk * 2 + ha;
            offA[mf][kk] = row * 64 + ((c ^ ((row >> 1) & 3)) << 4);
        }
    #pragma unroll
    for (int nf4 = 0; nf4 < 4; nf4++)
        #pragma unroll
        for (int kk = 0; kk < 2; kk++) {
            int row = warp_n * 64 + nf4 * 16 + rb;
            int c   = kk * 2 + hb;
            offB[nf4][kk] = 8192 + row * 64 + ((c ^ ((row >> 1) & 3)) << 4);
        }

    int crow[4], ccol[4];
    uint32_t csw[4];
    #pragma unroll
    for (int s = 0; s < 4; s++) {
        int q = s * 128 + tid;
        crow[s] = q >> 2; ccol[s] = q & 3;
        csw[s] = crow[s] * 64 + ((ccol[s] ^ ((crow[s] >> 1) & 3)) << 4);
    }

    float4 aA[4][2];
    auto ldgA = [&](int kg) {
        const int kgo = kg * 32;
        #pragma unroll
        for (int s = 0; s < 4; s++) {
            const float* gp = W2 + (size_t)(i0 + crow[s]) * HH + kgo + ccol[s] * 8;
            aA[s][0] = *(const float4*)gp;
            aA[s][1] = *(const float4*)(gp + 4);
        }
    };
    auto stsA = [&](int stage) {
        const uint32_t base = sbase + stage * K3_STG;
        #pragma unroll
        for (int s = 0; s < 4; s++) {
            __half2 h0 = __floats2half2_rn(aA[s][0].x, aA[s][0].y);
            __half2 h1 = __floats2half2_rn(aA[s][0].z, aA[s][0].w);
            __half2 h2 = __floats2half2_rn(aA[s][1].x, aA[s][1].y);
            __half2 h3 = __floats2half2_rn(aA[s][1].z, aA[s][1].w);
            STS128(base + csw[s], h2u(h0), h2u(h1), h2u(h2), h2u(h3));
        }
    };
    auto cpB = [&](int stage, int kg) {
        const uint32_t base = sbase + stage * K3_STG + 8192;
        const int kgo = kg * 32;
        #pragma unroll
        for (int s = 0; s < 4; s++)
            cp16(base + csw[s], g_BTh + (size_t)(j0 + crow[s]) * HH + kgo + ccol[s] * 8);
        cp_commit();
    };

    float acc[4][8][4];
    #pragma unroll
    for (int mf = 0; mf < 4; mf++)
        #pragma unroll
        for (int nf = 0; nf < 8; nf++)
            #pragma unroll
            for (int q = 0; q < 4; q++) acc[mf][nf][q] = 0.f;

    ldgA(0); stsA(0); cpB(0, 0);
    ldgA(1); stsA(1); cpB(1, 1);
    ldgA(2);

    for (int kg = 0; kg < NKG3; ++kg) {
        if (kg + 1 == NKG3) cp_wait<0>();
        else                cp_wait<1>();
        __syncthreads();
        if (kg + 2 < NKG3) {
            const int ps = (kg + 2) % 3;
            stsA(ps);
            if (kg + 3 < NKG3) ldgA(kg + 3);
            cpB(ps, kg + 2);
        }
        const uint32_t base = sbase + (kg % 3) * K3_STG;
        #pragma unroll
        for (int kk = 0; kk < 2; kk++) {
            uint32_t a[4][4], bh[8][2];
            #pragma unroll
            for (int mf = 0; mf < 4; mf++)
                LDSM4(a[mf][0], a[mf][1], a[mf][2], a[mf][3], base + offA[mf][kk]);
            #pragma unroll
            for (int nf4 = 0; nf4 < 4; nf4++) {
                uint32_t r0, r1, r2, r3;
                LDSM4(r0, r1, r2, r3, base + offB[nf4][kk]);
                bh[nf4 * 2][0] = r0;     bh[nf4 * 2][1] = r1;
                bh[nf4 * 2 + 1][0] = r2; bh[nf4 * 2 + 1][1] = r3;
            }
            #pragma unroll
            for (int mf = 0; mf < 4; mf++)
                #pragma unroll
                for (int nf = 0; nf < 8; nf++)
                    MMA16816F(acc[mf][nf], a[mf], bh[nf]);
        }
    }

    // epilogue: store E2 tile + fused per-row |.| partial sums
    const int er = lane >> 2;
    const int ec = (lane & 3) * 2;
    #pragma unroll
    for (int mf = 0; mf < 4; mf++) {
        float sa = 0.f, sb = 0.f;
        #pragma unroll
        for (int nf = 0; nf < 8; nf++) {
            int row = i0 + warp_m * 64 + mf * 16 + er;
            int col = j0 + warp_n * 64 + nf * 8 + ec;
            *(float2*)(g_E2s + (size_t)row * NE + col)       = make_float2(acc[mf][nf][0], acc[mf][nf][1]);
            *(float2*)(g_E2s + (size_t)(row + 8) * NE + col) = make_float2(acc[mf][nf][2], acc[mf][nf][3]);
            sa += fabsf(acc[mf][nf][0]) + fabsf(acc[mf][nf][1]);
            sb += fabsf(acc[mf][nf][2]) + fabsf(acc[mf][nf][3]);
        }
        sa += __shfl_xor_sync(0xffffffffu, sa, 1);
        sa += __shfl_xor_sync(0xffffffffu, sa, 2);
        sb += __shfl_xor_sync(0xffffffffu, sb, 1);
        sb += __shfl_xor_sync(0xffffffffu, sb, 2);
        if ((lane & 3) == 0) {
            rs[warp_n][warp_m * 64 + mf * 16 + er]     = sa;
            rs[warp_n][warp_m * 64 + mf * 16 + 8 + er] = sb;
        }
    }
    __syncthreads();
    {
        int row = tid;
        float v = rs[0][row] + rs[1][row];
        g_rpart[blockIdx.x][i0 + row] = v;
    }
}

// ---- K5: layer-3 partial GEMM with INLINE ReLU-param computation ----
__global__ void k5_e3(const float* __restrict__ W3, const float* __restrict__ b2) {
    __shared__ float w3s[OO][128];
    __shared__ float s2s[128];
    __shared__ float t2s[128];
    __shared__ float v2s[128];
    const int jt = blockIdx.x, ks = blockIdx.y;
    const int k0 = ks * 128;
    const int tid = threadIdx.x;

    // inline relu params for this k-chunk (was k4)
    {
        int row = k0 + tid;
        float sr = 0.f;
        #pragma unroll
        for (int p = 0; p < NJT; p++) sr += g_rpart[p][row];
        sr += fabsf(g_tcol[row]);
        float v = g_vcol[row] + b2[row];
        float s, t, vn;
        relu_params(v, sr, s, t, vn);
        s2s[tid] = s; t2s[tid] = t; v2s[tid] = vn;
    }
    for (int idx = tid; idx < OO * 128; idx += 128) {
        int i = idx >> 7, kk = idx & 127;
        w3s[i][kk] = W3[(size_t)i * HH + k0 + kk];
    }
    __syncthreads();

    const int j = jt * 128 + tid;
    float acc[OO];
    #pragma unroll
    for (int i = 0; i < OO; i++) acc[i] = 0.f;

    if (j < 1024) {
        const float* e = g_E2s + (size_t)k0 * NE + j;
        for (int kk = 0; kk < 128; ++kk) {
            float bval = s2s[kk] * e[(size_t)kk * NE];
            #pragma unroll
            for (int i = 0; i < OO; i++) acc[i] += w3s[i][kk] * bval;
        }
    } else if (j == 1024) {
        for (int kk = 0; kk < 128; ++kk) {
            float bval = s2s[kk] * g_tcol[k0 + kk];
            #pragma unroll
            for (int i = 0; i < OO; i++) acc[i] += w3s[i][kk] * bval;
        }
    } else if (j == 1025) {
        for (int kk = 0; kk < 128; ++kk) {
            float bval = t2s[kk];
            #pragma unroll
            for (int i = 0; i < OO; i++) acc[i] += w3s[i][kk] * bval;
        }
    } else if (j == 1026) {
        for (int kk = 0; kk < 128; ++kk) {
            float bval = v2s[kk];
            #pragma unroll
            for (int i = 0; i < OO; i++) acc[i] += w3s[i][kk] * bval;
        }
    }
    if (j < NC3) {
        #pragma unroll
        for (int i = 0; i < OO; i++)
            g_E3p[((size_t)ks * OO + i) * SE3 + j] = acc[i];
    }
}

// ---- K6 ----
__global__ void k6_final(const float* __restrict__ b3, float* __restrict__ out) {
    const int i = blockIdx.x;
    const int tid = threadIdx.x;
    __shared__ float red[256];
    __shared__ float vsh;
    float racc = 0.f;
    for (int j = tid; j < NC3; j += 256) {
        float s = 0.f;
        #pragma unroll
        for (int ks = 0; ks < KS3; ks++) s += g_E3p[((size_t)ks * OO + i) * SE3 + j];
        if (j < 1026) racc += fabsf(s);
        else          vsh = s + b3[i];
    }
    red[tid] = racc;
    __syncthreads();
    for (int o = 128; o; o >>= 1) {
        if (tid < o) red[tid] += red[tid + o];
        __syncthreads();
    }
    if (tid == 0) {
        float v = vsh, r = red[0];
        out[i]      = v + r;
        out[10 + i] = v - r;
    }
}

extern "C" void kernel_launch(void* const* d_in, const int* in_sizes, int n_in,
                              void* d_out, int out_size) {
    const float* inputs = (const float*)d_in[0];
    const float* W1     = (const float*)d_in[1];
    const float* b1     = (const float*)d_in[2];
    const float* W2     = (const float*)d_in[3];
    const float* b2     = (const float*)d_in[4];
    const float* W3     = (const float*)d_in[5];
    const float* b3     = (const float*)d_in[6];
    float* out = (float*)d_out;

    static cudaStream_t sB = nullptr;
    static cudaEvent_t evK = nullptr, evB = nullptr;
    if (!sB) {
        cudaStreamCreateWithFlags(&sB, cudaStreamNonBlocking);
        cudaEventCreateWithFlags(&evK, cudaEventDisableTiming);
        cudaEventCreateWithFlags(&evB, cudaEventDisableTiming);
        cudaFuncSetAttribute(k3_mma, cudaFuncAttributeMaxDynamicSharedMemorySize, K3_SMEM);
    }

    // main chain
    k01_layer1<<<HH / 8, 256>>>(inputs, W1, b1);

    // fork: t/v matvec on side stream (needs k01 only)
    cudaEventRecord(evK, 0);
    cudaStreamWaitEvent(sB, evK, 0);
    k3b_tv<<<HH / 8, 256, 0, sB>>>(W2);
    cudaEventRecord(evB, sB);

    dim3 g2b(HH / 64, DD / 64);           // 64 x 16 = 1024 blocks
    k2b_buildBT<<<g2b, 256>>>(W1);

    dim3 g3(NE / 128, HH / 128);          // 256 CTAs, occ 2
    k3_mma<<<g3, 128, K3_SMEM>>>(W2);

    cudaStreamWaitEvent(0, evB, 0);       // k5 needs tcol/vcol
    dim3 g5(9, KS3);
    k5_e3<<<g5, 128>>>(W3, b2);
    k6_final<<<OO, 256>>>(b3, out);
}